// round 2
// baseline (speedup 1.0000x reference)
#include <cuda_runtime.h>
#include <math.h>

// Problem constants
#define ID 56           // input spatial
#define OD 52           // output spatial (VALID 5x5x5)
#define NCH 64          // channels in = out
#define TILE 4          // output voxels per block per dim
#define NBLK 13         // 52/4

// Precomputed conv kernel, layout [tap(125)][in(64)][out(64)]
__device__ float g_K[125 * 64 * 64];

// ---------------------------------------------------------------------------
// Prep kernel: synthesize the 5x5x5x64x64 kernel from weight + fold in the
// center-tap self-connection (w_sc0 scalar block, w_sc1 * I3 vector block).
// grid = 125 blocks (one per tap), 256 threads (one per (u, w) pair).
// ---------------------------------------------------------------------------
__global__ void build_kernel(const float* __restrict__ weight,   // [5,1024]
                             const float* __restrict__ w_sc0,    // [16,16]
                             const float* __restrict__ w_sc1) {  // [16,16]
    const int tap = blockIdx.x;            // 0..124
    const int i = tap / 25, j = (tap / 5) % 5, k = tap % 5;
    const float rr[5] = {-1.0f, -0.5f, 0.0f, 0.5f, 1.0f};
    const float ri = rr[i], rj = rr[j], rk = rr[k];
    const float d = sqrtf(ri * ri + rj * rj + rk * rk);

    // emb[t] = 1.14136 * e^2 * sus(diff+1) * sus(1-diff), diff = 4d - t
    float emb[5];
    const float C = 1.14136f * 7.389056098930650f;  // 1.14136 * e^2
    #pragma unroll
    for (int t = 0; t < 5; t++) {
        float diff = 4.0f * d - (float)t;
        float t1 = diff + 1.0f;
        float t2 = 1.0f - diff;
        float s1 = (t1 > 0.0f) ? expf(-1.0f / t1) : 0.0f;
        float s2 = (t2 > 0.0f) ? expf(-1.0f / t2) : 0.0f;
        emb[t] = C * s1 * s2;
    }
    const float dn = fmaxf(d, 1e-12f);
    const float SQ3 = 1.7320508075688772f;
    const float sh1_0 = SQ3 * ri / dn;
    const float sh1_1 = SQ3 * rj / dn;
    const float sh1_2 = SQ3 * rk / dn;
    float sh1[3] = {sh1_0, sh1_1, sh1_2};

    const int tid = threadIdx.x;           // 0..255
    const int u  = tid >> 4;               // input mul index 0..15
    const int wc = tid & 15;               // output mul index 0..15
    const int col = u * 16 + wc;

    float w1 = 0.f, w2 = 0.f, w3 = 0.f, w4 = 0.f;
    #pragma unroll
    for (int t = 0; t < 5; t++) {
        float e = emb[t];
        w1 += e * weight[t * 1024 +   0 + col];
        w2 += e * weight[t * 1024 + 256 + col];
        w3 += e * weight[t * 1024 + 512 + col];
        w4 += e * weight[t * 1024 + 768 + col];
    }

    const float PW0 = 0.17677669529663687f;  // sqrt(1/32)
    const float PW1 = 0.30618621784789724f;  // sqrt(3/32)
    const float IS3 = 0.57735026918962576f;  // 1/sqrt(3)
    const bool center = (tap == 62);         // (2,2,2): fold sc here (crop=2)
    float* Kt = g_K + tap * 4096;            // [in][out]

    // scalar -> scalar
    float vss = PW0 * w1;
    if (center) vss += 0.25f * w_sc0[u * 16 + wc];
    Kt[u * 64 + wc] = vss;

    // scalar(in u) -> vector(out 16 + wc*3 + kc)
    #pragma unroll
    for (int kc = 0; kc < 3; kc++)
        Kt[u * 64 + 16 + wc * 3 + kc] = PW1 * IS3 * w2 * sh1[kc];

    // vector(in 16 + u*3 + ic) -> scalar(out wc)
    #pragma unroll
    for (int ic = 0; ic < 3; ic++)
        Kt[(16 + u * 3 + ic) * 64 + wc] = PW0 * IS3 * w4 * sh1[ic];

    // vector -> vector: delta_{ic,jc} * (PW1/sqrt3 * w3)  (+ center w_sc1/4)
    float vvdiag = PW1 * IS3 * w3;
    if (center) vvdiag += 0.25f * w_sc1[u * 16 + wc];
    #pragma unroll
    for (int ic = 0; ic < 3; ic++)
        #pragma unroll
        for (int jc = 0; jc < 3; jc++)
            Kt[(16 + u * 3 + ic) * 64 + (16 + wc * 3 + jc)] =
                (ic == jc) ? vvdiag : 0.0f;
}

// ---------------------------------------------------------------------------
// Main conv: GEMM-style direct conv.
// Block: 4x4x4 output voxels x 64 out channels. 256 threads, each 4x4 accs.
// Smem: full 8x8x8 x 64ch input window (z-skewed, 139KB) + per-(kd,kh)
//       weight slab of 5 taps (80KB).
// ---------------------------------------------------------------------------
#define SIN_ZSTR 68          // 64 + 4-float skew: breaks LDS bank conflicts
#define SIN_CSTR (8 * SIN_ZSTR)   // 544 floats per channel
#define SIN_FLOATS (64 * SIN_CSTR) // 34816
#define SW_FLOATS (5 * 64 * 64)    // 20480
#define SMEM_BYTES ((SIN_FLOATS + SW_FLOATS) * 4)  // 221184

__global__ void __launch_bounds__(256, 1)
conv_kernel(const float* __restrict__ x, float* __restrict__ out) {
    extern __shared__ float sm[];
    float* sIn = sm;                  // [c][z(68)][y(8)][x(8)] skewed
    float* sW  = sm + SIN_FLOATS;     // [kw(5)][c(64)][o(64)]

    const int tid = threadIdx.x;
    const int x0 = blockIdx.x * TILE;
    const int y0 = blockIdx.y * TILE;
    const int z0 = blockIdx.z * TILE;

    // ---- stage input window: 64ch x 8x8x8, vectorized float4 ----
    #pragma unroll
    for (int it = 0; it < 32; it++) {
        int idx = tid + it * 256;          // 0..8191 float4s
        int c   = idx >> 7;
        int rem = idx & 127;
        int z   = rem >> 4;
        int y   = (rem >> 1) & 7;
        int h   = rem & 1;                 // which half of the 8-float row
        const float4 v = *(const float4*)(
            x + (((size_t)c * ID + (z0 + z)) * ID + (y0 + y)) * ID + x0 + h * 4);
        *(float4*)&sIn[c * SIN_CSTR + z * SIN_ZSTR + y * 8 + h * 4] = v;
    }

    const int tx = tid & 15;          // out-channel group: o = tx*4 + n
    const int ty = tid >> 4;          // voxel group
    const int vz = ty >> 2;
    const int vy = ty & 3;

    float acc[4][4];
    #pragma unroll
    for (int m = 0; m < 4; m++)
        #pragma unroll
        for (int n = 0; n < 4; n++)
            acc[m][n] = 0.0f;

    #pragma unroll 1
    for (int kd = 0; kd < 5; kd++) {
        #pragma unroll 1
        for (int kh = 0; kh < 5; kh++) {
            __syncthreads();   // protect previous slab's sW reads
            // stage weight slab: taps (kd,kh,0..4) -> 5120 float4 from L2
            {
                const float4* gw =
                    (const float4*)(g_K + (kd * 25 + kh * 5) * 4096);
                float4* sw4 = (float4*)sW;
                #pragma unroll
                for (int it = 0; it < 20; it++)
                    sw4[tid + it * 256] = gw[tid + it * 256];
            }
            __syncthreads();   // sW ready (also guards sIn on first iter)

            const float* rowbase = &sIn[(vz + kd) * SIN_ZSTR + (vy + kh) * 8];
            #pragma unroll 4
            for (int c = 0; c < 64; c++) {
                const float* rp = rowbase + c * SIN_CSTR;
                const float4 a0 = *(const float4*)rp;
                const float4 a1 = *(const float4*)(rp + 4);
                const float a[8] = {a0.x, a0.y, a0.z, a0.w,
                                    a1.x, a1.y, a1.z, a1.w};
                #pragma unroll
                for (int kw = 0; kw < 5; kw++) {
                    const float4 b =
                        *(const float4*)&sW[kw * 4096 + c * 64 + tx * 4];
                    const float bn[4] = {b.x, b.y, b.z, b.w};
                    #pragma unroll
                    for (int m = 0; m < 4; m++)
                        #pragma unroll
                        for (int n = 0; n < 4; n++)
                            acc[m][n] += a[kw + m] * bn[n];
                }
            }
        }
    }

    // ---- epilogue: out[o][z][y][x] ----
    const size_t sp = ((size_t)(z0 + vz) * OD + (y0 + vy)) * OD + x0;
    #pragma unroll
    for (int n = 0; n < 4; n++) {
        const int o = tx * 4 + n;
        float* op = out + (size_t)o * OD * OD * OD + sp;
        #pragma unroll
        for (int m = 0; m < 4; m++)
            op[m] = acc[m][n];
    }
}

// ---------------------------------------------------------------------------
extern "C" void kernel_launch(void* const* d_in, const int* in_sizes, int n_in,
                              void* d_out, int out_size) {
    const float* x      = (const float*)d_in[0];  // (1,64,56,56,56)
    const float* weight = (const float*)d_in[1];  // (5,1024)
    const float* w_sc0  = (const float*)d_in[2];  // (16,16)
    const float* w_sc1  = (const float*)d_in[3];  // (16,16)
    float* out = (float*)d_out;                   // (1,64,52,52,52)

    build_kernel<<<125, 256>>>(weight, w_sc0, w_sc1);

    cudaFuncSetAttribute(conv_kernel,
                         cudaFuncAttributeMaxDynamicSharedMemorySize,
                         SMEM_BYTES);
    dim3 grid(NBLK, NBLK, NBLK);
    conv_kernel<<<grid, 256, SMEM_BYTES>>>(x, out);
}

// round 3
// speedup vs baseline: 1.0538x; 1.0538x over previous
#include <cuda_runtime.h>
#include <math.h>

// Problem constants
#define ID 56           // input spatial
#define OD 52           // output spatial (VALID 5x5x5)
#define NCH 64          // channels in = out
#define TILE 4          // output voxels per block per dim
#define NBLK 13         // 52/4

// Precomputed conv kernel, layout [tap(125)][in(64)][out(64)]
__device__ float g_K[125 * 64 * 64];

// ---------------------------------------------------------------------------
// Prep kernel: synthesize the 5x5x5x64x64 kernel from weight + fold in the
// center-tap self-connection (w_sc0 scalar block, w_sc1 * I3 vector block).
// grid = 125 blocks (one per tap), 256 threads (one per (u, w) pair).
// ---------------------------------------------------------------------------
__global__ void build_kernel(const float* __restrict__ weight,   // [5,1024]
                             const float* __restrict__ w_sc0,    // [16,16]
                             const float* __restrict__ w_sc1) {  // [16,16]
    const int tap = blockIdx.x;            // 0..124
    const int i = tap / 25, j = (tap / 5) % 5, k = tap % 5;
    const float rr[5] = {-1.0f, -0.5f, 0.0f, 0.5f, 1.0f};
    const float ri = rr[i], rj = rr[j], rk = rr[k];
    const float d = sqrtf(ri * ri + rj * rj + rk * rk);

    // emb[t] = 1.14136 * e^2 * sus(diff+1) * sus(1-diff), diff = 4d - t
    float emb[5];
    const float C = 1.14136f * 7.389056098930650f;  // 1.14136 * e^2
    #pragma unroll
    for (int t = 0; t < 5; t++) {
        float diff = 4.0f * d - (float)t;
        float t1 = diff + 1.0f;
        float t2 = 1.0f - diff;
        float s1 = (t1 > 0.0f) ? expf(-1.0f / t1) : 0.0f;
        float s2 = (t2 > 0.0f) ? expf(-1.0f / t2) : 0.0f;
        emb[t] = C * s1 * s2;
    }
    const float dn = fmaxf(d, 1e-12f);
    const float SQ3 = 1.7320508075688772f;
    const float sh1_0 = SQ3 * ri / dn;
    const float sh1_1 = SQ3 * rj / dn;
    const float sh1_2 = SQ3 * rk / dn;
    float sh1[3] = {sh1_0, sh1_1, sh1_2};

    const int tid = threadIdx.x;           // 0..255
    const int u  = tid >> 4;               // input mul index 0..15
    const int wc = tid & 15;               // output mul index 0..15
    const int col = u * 16 + wc;

    float w1 = 0.f, w2 = 0.f, w3 = 0.f, w4 = 0.f;
    #pragma unroll
    for (int t = 0; t < 5; t++) {
        float e = emb[t];
        w1 += e * weight[t * 1024 +   0 + col];
        w2 += e * weight[t * 1024 + 256 + col];
        w3 += e * weight[t * 1024 + 512 + col];
        w4 += e * weight[t * 1024 + 768 + col];
    }

    const float PW0 = 0.17677669529663687f;  // sqrt(1/32)
    const float PW1 = 0.30618621784789724f;  // sqrt(3/32)
    const float IS3 = 0.57735026918962576f;  // 1/sqrt(3)
    const bool center = (tap == 62);         // (2,2,2): fold sc here (crop=2)
    float* Kt = g_K + tap * 4096;            // [in][out]

    // scalar -> scalar
    float vss = PW0 * w1;
    if (center) vss += 0.25f * w_sc0[u * 16 + wc];
    Kt[u * 64 + wc] = vss;

    // scalar(in u) -> vector(out 16 + wc*3 + kc)
    #pragma unroll
    for (int kc = 0; kc < 3; kc++)
        Kt[u * 64 + 16 + wc * 3 + kc] = PW1 * IS3 * w2 * sh1[kc];

    // vector(in 16 + u*3 + ic) -> scalar(out wc)
    #pragma unroll
    for (int ic = 0; ic < 3; ic++)
        Kt[(16 + u * 3 + ic) * 64 + wc] = PW0 * IS3 * w4 * sh1[ic];

    // vector -> vector: delta_{ic,jc} * (PW1/sqrt3 * w3)  (+ center w_sc1/4)
    float vvdiag = PW1 * IS3 * w3;
    if (center) vvdiag += 0.25f * w_sc1[u * 16 + wc];
    #pragma unroll
    for (int ic = 0; ic < 3; ic++)
        #pragma unroll
        for (int jc = 0; jc < 3; jc++)
            Kt[(16 + u * 3 + ic) * 64 + (16 + wc * 3 + jc)] =
                (ic == jc) ? vvdiag : 0.0f;
}

// ---------------------------------------------------------------------------
// Main conv: GEMM-style direct conv.
// Block: 4x4x4 output voxels x 64 out channels. 256 threads, each 4x4 accs.
// Smem: full 8x8x8 x 64ch input window (z-skewed, 139KB) + per-(kd,kh)
//       weight slab of 5 taps (80KB).
// ---------------------------------------------------------------------------
#define SIN_ZSTR 68          // 64 + 4-float skew: breaks LDS bank conflicts
#define SIN_CSTR (8 * SIN_ZSTR)   // 544 floats per channel
#define SIN_FLOATS (64 * SIN_CSTR) // 34816
#define SW_FLOATS (5 * 64 * 64)    // 20480
#define SMEM_BYTES ((SIN_FLOATS + SW_FLOATS) * 4)  // 221184

__global__ void __launch_bounds__(256, 1)
conv_kernel(const float* __restrict__ x, float* __restrict__ out) {
    extern __shared__ float sm[];
    float* sIn = sm;                  // [c][z(68)][y(8)][x(8)] skewed
    float* sW  = sm + SIN_FLOATS;     // [kw(5)][c(64)][o(64)]

    const int tid = threadIdx.x;
    const int x0 = blockIdx.x * TILE;
    const int y0 = blockIdx.y * TILE;
    const int z0 = blockIdx.z * TILE;

    // ---- stage input window: 64ch x 8x8x8, vectorized float4 ----
    #pragma unroll
    for (int it = 0; it < 32; it++) {
        int idx = tid + it * 256;          // 0..8191 float4s
        int c   = idx >> 7;
        int rem = idx & 127;
        int z   = rem >> 4;
        int y   = (rem >> 1) & 7;
        int h   = rem & 1;                 // which half of the 8-float row
        const float4 v = *(const float4*)(
            x + (((size_t)c * ID + (z0 + z)) * ID + (y0 + y)) * ID + x0 + h * 4);
        *(float4*)&sIn[c * SIN_CSTR + z * SIN_ZSTR + y * 8 + h * 4] = v;
    }

    const int tx = tid & 15;          // out-channel group: o = tx*4 + n
    const int ty = tid >> 4;          // voxel group
    const int vz = ty >> 2;
    const int vy = ty & 3;

    float acc[4][4];
    #pragma unroll
    for (int m = 0; m < 4; m++)
        #pragma unroll
        for (int n = 0; n < 4; n++)
            acc[m][n] = 0.0f;

    #pragma unroll 1
    for (int kd = 0; kd < 5; kd++) {
        #pragma unroll 1
        for (int kh = 0; kh < 5; kh++) {
            __syncthreads();   // protect previous slab's sW reads
            // stage weight slab: taps (kd,kh,0..4) -> 5120 float4 from L2
            {
                const float4* gw =
                    (const float4*)(g_K + (kd * 25 + kh * 5) * 4096);
                float4* sw4 = (float4*)sW;
                #pragma unroll
                for (int it = 0; it < 20; it++)
                    sw4[tid + it * 256] = gw[tid + it * 256];
            }
            __syncthreads();   // sW ready (also guards sIn on first iter)

            const float* rowbase = &sIn[(vz + kd) * SIN_ZSTR + (vy + kh) * 8];
            #pragma unroll 4
            for (int c = 0; c < 64; c++) {
                const float* rp = rowbase + c * SIN_CSTR;
                const float4 a0 = *(const float4*)rp;
                const float4 a1 = *(const float4*)(rp + 4);
                const float a[8] = {a0.x, a0.y, a0.z, a0.w,
                                    a1.x, a1.y, a1.z, a1.w};
                #pragma unroll
                for (int kw = 0; kw < 5; kw++) {
                    const float4 b =
                        *(const float4*)&sW[kw * 4096 + c * 64 + tx * 4];
                    const float bn[4] = {b.x, b.y, b.z, b.w};
                    #pragma unroll
                    for (int m = 0; m < 4; m++)
                        #pragma unroll
                        for (int n = 0; n < 4; n++)
                            acc[m][n] += a[kw + m] * bn[n];
                }
            }
        }
    }

    // ---- epilogue: out[o][z][y][x] ----
    const size_t sp = ((size_t)(z0 + vz) * OD + (y0 + vy)) * OD + x0;
    #pragma unroll
    for (int n = 0; n < 4; n++) {
        const int o = tx * 4 + n;
        float* op = out + (size_t)o * OD * OD * OD + sp;
        #pragma unroll
        for (int m = 0; m < 4; m++)
            op[m] = acc[m][n];
    }
}

// ---------------------------------------------------------------------------
extern "C" void kernel_launch(void* const* d_in, const int* in_sizes, int n_in,
                              void* d_out, int out_size) {
    const float* x      = (const float*)d_in[0];  // (1,64,56,56,56)
    const float* weight = (const float*)d_in[1];  // (5,1024)
    const float* w_sc0  = (const float*)d_in[2];  // (16,16)
    const float* w_sc1  = (const float*)d_in[3];  // (16,16)
    float* out = (float*)d_out;                   // (1,64,52,52,52)

    build_kernel<<<125, 256>>>(weight, w_sc0, w_sc1);

    cudaFuncSetAttribute(conv_kernel,
                         cudaFuncAttributeMaxDynamicSharedMemorySize,
                         SMEM_BYTES);
    dim3 grid(NBLK, NBLK, NBLK);
    conv_kernel<<<grid, 256, SMEM_BYTES>>>(x, out);
}

// round 10
// speedup vs baseline: 7.7331x; 7.3380x over previous
#include <cuda_runtime.h>
#include <cuda_fp16.h>
#include <cstdint>
#include <math.h>

#define ID 56
#define OD 52
#define NSITE (ID*ID*ID)           // 175616
#define OSZ (OD*OD*OD)             // 140608
#define YW 8                       // window y rows (4 out rows + 4)
#define ROWB 80                    // bytes per site row (32ch fp16 = 64B + 16B pad)
#define WINB (5*YW*ID*ROWB)        // 179200
#define SLABB (5*64*ROWB)          // 25600 (5 taps x 64 out x 80B)
#define CTRL 512
#define SMEMB (CTRL + WINB + 2*SLABB)   // 230912
#define WCHB (125*64*ROWB)         // 640000 bytes per weight chunk
#define XCHW (NSITE*20)            // uint32 words per x chunk

__device__ __align__(1024) __half g_xh[2u*NSITE*40];   // [chunk][site][40 halves]
__device__ __align__(1024) __half g_Wh[2u*125*64*40];  // [chunk][tap][o][40 halves]

__device__ __forceinline__ uint32_t s2u(const void* p){
    uint32_t a; asm("{ .reg .u64 t; cvta.to.shared.u64 t, %1; cvt.u32.u64 %0, t; }":"=r"(a):"l"(p)); return a;
}
#define MBAR_INIT(a,c) asm volatile("mbarrier.init.shared.b64 [%0], %1;"::"r"(a),"r"(c):"memory")
#define MBAR_TX(a,b)   asm volatile("mbarrier.arrive.expect_tx.shared.b64 _, [%0], %1;"::"r"(a),"r"(b):"memory")
#define MBAR_WAIT(a,p) do{ uint32_t _m=(a),_p=(p); asm volatile( \
    "{\n\t.reg .pred P;\n\tW%=:\n\t" \
    "mbarrier.try_wait.parity.acquire.cta.shared::cta.b64 P, [%0], %1, 0x989680;\n\t" \
    "@P bra.uni D%=;\n\tbra.uni W%=;\n\tD%=:\n\t}"::"r"(_m),"r"(_p):"memory"); }while(0)
#define BULK(dst,src,n,mb) asm volatile( \
    "cp.async.bulk.shared::cluster.global.mbarrier::complete_tx::bytes [%0], [%1], %2, [%3];" \
    ::"r"(dst),"l"(src),"r"(n),"r"(mb):"memory")

#define LDSM_X4(r, a) asm volatile( \
    "ldmatrix.sync.aligned.m8n8.x4.shared.b16 {%0,%1,%2,%3}, [%4];" \
    : "=r"((r)[0]),"=r"((r)[1]),"=r"((r)[2]),"=r"((r)[3]) : "r"(a))

#define MMA16816(d, a, b) asm volatile( \
    "mma.sync.aligned.m16n8k16.row.col.f32.f16.f16.f32 " \
    "{%0,%1,%2,%3}, {%4,%5,%6,%7}, {%8,%9}, {%0,%1,%2,%3};" \
    : "+f"((d)[0]),"+f"((d)[1]),"+f"((d)[2]),"+f"((d)[3]) \
    : "r"((a)[0]),"r"((a)[1]),"r"((a)[2]),"r"((a)[3]), "r"((b)[0]),"r"((b)[1]))

// ---------------- prep: weights -> fp16 [chunk][tap][o64][c32 +pad] --------
__global__ void build_w(const float* __restrict__ weight,
                        const float* __restrict__ w_sc0,
                        const float* __restrict__ w_sc1){
    const int tap = blockIdx.x;
    const int i = tap/25, j = (tap/5)%5, k = tap%5;
    const float rr[5] = {-1.f,-0.5f,0.f,0.5f,1.f};
    const float ri=rr[i], rj=rr[j], rk=rr[k];
    const float d = sqrtf(ri*ri+rj*rj+rk*rk);
    float emb[5]; const float C = 1.14136f*7.389056098930650f;
    #pragma unroll
    for (int t=0;t<5;t++){
        float diff = 4.f*d - (float)t;
        float t1 = diff+1.f, t2 = 1.f-diff;
        float s1 = (t1>0.f)?expf(-1.f/t1):0.f;
        float s2 = (t2>0.f)?expf(-1.f/t2):0.f;
        emb[t] = C*s1*s2;
    }
    const float dn = fmaxf(d,1e-12f);
    const float SQ3 = 1.7320508075688772f;
    float sh[3] = {SQ3*ri/dn, SQ3*rj/dn, SQ3*rk/dn};
    const int tid = threadIdx.x, u = tid>>4, wc = tid&15, col = u*16+wc;
    float w1=0,w2=0,w3=0,w4=0;
    #pragma unroll
    for (int t=0;t<5;t++){
        float e = emb[t];
        w1 += e*weight[t*1024+  0+col]; w2 += e*weight[t*1024+256+col];
        w3 += e*weight[t*1024+512+col]; w4 += e*weight[t*1024+768+col];
    }
    const float PW0=0.17677669529663687f, PW1=0.30618621784789724f, IS3=0.57735026918962576f;
    const bool center = (tap==62);
    auto put = [&](int ci, int o, float v){
        int ch = ci>>5, c = ci&31;
        g_Wh[(((uint32_t)ch*125 + tap)*64 + o)*40 + c] = __float2half(v);
    };
    float vss = PW0*w1; if (center) vss += 0.25f*w_sc0[u*16+wc];
    put(u, wc, vss);
    #pragma unroll
    for (int kc=0;kc<3;kc++) put(u, 16+wc*3+kc, PW1*IS3*w2*sh[kc]);
    #pragma unroll
    for (int ic=0;ic<3;ic++) put(16+u*3+ic, wc, PW0*IS3*w4*sh[ic]);
    float vv = PW1*IS3*w3; if (center) vv += 0.25f*w_sc1[u*16+wc];
    #pragma unroll
    for (int ic=0;ic<3;ic++)
        #pragma unroll
        for (int jc=0;jc<3;jc++)
            put(16+u*3+ic, 16+wc*3+jc, (ic==jc)?vv:0.f);
}

// ------------- prep: x -> fp16 [chunk][site][32ch + pad] (80B rows) --------
__global__ void __launch_bounds__(256) conv_x(const float* __restrict__ x){
    __shared__ uint32_t sb[16][514];
    const int chunk = blockIdx.y;
    const int site0 = blockIdx.x*512;
    const int tid = threadIdx.x;
    #pragma unroll
    for (int p=0;p<16;p++){
        const float* a = x + (size_t)(chunk*32+2*p)*NSITE + site0;
        const float* b = a + NSITE;
        sb[p][tid]     = ((uint32_t)__half_as_ushort(__float2half(a[tid]))) |
                         ((uint32_t)__half_as_ushort(__float2half(b[tid]))<<16);
        sb[p][tid+256] = ((uint32_t)__half_as_ushort(__float2half(a[tid+256]))) |
                         ((uint32_t)__half_as_ushort(__float2half(b[tid+256]))<<16);
    }
    __syncthreads();
    uint32_t* dst = (uint32_t*)g_xh + (uint32_t)chunk*XCHW;
    #pragma unroll
    for (int it=0;it<32;it++){
        int jdx = tid + it*256;
        int sl = jdx>>4, p = jdx&15;
        dst[(uint32_t)(site0+sl)*20u + p] = sb[p][sl];
    }
}

// ---------------------------- main HMMA conv -------------------------------
__global__ void __launch_bounds__(256,1) conv_mma(float* __restrict__ out){
    extern __shared__ __align__(1024) char sm[];
    const uint32_t smb = s2u(sm);
    const int tid = threadIdx.x, w = tid>>5, l = tid&31;
    const uint32_t mb_win = smb, mb_s0 = smb+8, mb_s1 = smb+16;
    const uint32_t win = smb + CTRL;
    const uint32_t slab0 = win + WINB, slab1 = slab0 + SLABB;

    if (tid==0){ MBAR_INIT(mb_win,1); MBAR_INIT(mb_s0,1); MBAR_INIT(mb_s1,1); }
    __syncthreads();

    const int y0 = blockIdx.x*4, z0 = blockIdx.y;
    const char* gW = (const char*)g_Wh;
    const char* gX = (const char*)g_xh;

    if (tid==0){
        MBAR_TX(mb_win, WINB);
        #pragma unroll
        for (int dz=0;dz<5;dz++)
            BULK(win + dz*(YW*ID*ROWB),
                 gX + (size_t)(((z0+dz)*ID + y0)*ID)*ROWB, YW*ID*ROWB, mb_win);
        MBAR_TX(mb_s0, SLABB); BULK(slab0, gW, SLABB, mb_s0);
        MBAR_TX(mb_s1, SLABB); BULK(slab1, gW + SLABB, SLABB, mb_s1);
    }

    // acc[mt][nt][4] : M=32 per warp (2 m-tiles), N=64 (8 n-tiles)
    float acc[2][8][4];
    #pragma unroll
    for (int mt=0;mt<2;mt++)
        #pragma unroll
        for (int nt=0;nt<8;nt++)
            #pragma unroll
            for (int q=0;q<4;q++) acc[mt][nt][q] = 0.f;

    // lane-constant ldmatrix base addresses
    const uint32_t aLane = win + ((uint32_t)w*32 + (l&15))*ROWB + (l>>4)*16;
    const uint32_t bLane = ((uint32_t)((l&7) + ((l&16)>>1)))*ROWB + ((l&8)<<1);

    for (int chunk=0; chunk<2; chunk++){
        MBAR_WAIT(mb_win, chunk);
        for (int s=0;s<25;s++){
            const int i = chunk*25 + s;
            MBAR_WAIT(smb + 8 + (i&1)*8, (i>>1)&1);
            const uint32_t sl = (i&1) ? slab1 : slab0;
            #pragma unroll
            for (int jt=0;jt<5;jt++){
                const int t = s*5 + jt;
                const int dz = t/25, dy = (t/5)%5, dx = t%5;
                const uint32_t aTap = aLane + (uint32_t)(((dz*YW+dy)*ID + dx))*ROWB;
                const uint32_t bTap = sl + (uint32_t)jt*(64*ROWB) + bLane;
                #pragma unroll
                for (int kk=0;kk<2;kk++){
                    uint32_t bf[16];
                    #pragma unroll
                    for (int g=0; g<4; g++)
                        LDSM_X4(bf + g*4, bTap + kk*32 + g*(16*ROWB));
                    #pragma unroll
                    for (int mt=0; mt<2; mt++){
                        uint32_t af[4];
                        LDSM_X4(af, aTap + kk*32 + mt*(16*ROWB));
                        #pragma unroll
                        for (int nt=0; nt<8; nt++)
                            MMA16816(acc[mt][nt], af, bf + nt*2);
                    }
                }
            }
            __syncthreads();
            if (tid==0 && i+2 < 50){
                const int nslab = i+2;
                const uint32_t buf = (i&1) ? slab1 : slab0;
                MBAR_TX(smb + 8 + (i&1)*8, SLABB);
                BULK(buf, gW + (size_t)(nslab/25)*WCHB + (size_t)(nslab%25)*SLABB,
                     SLABB, smb + 8 + (i&1)*8);
            }
        }
        if (chunk==0 && tid==0){
            MBAR_TX(mb_win, WINB);
            #pragma unroll
            for (int dz=0;dz<5;dz++)
                BULK(win + dz*(YW*ID*ROWB),
                     gX + (size_t)NSITE*ROWB
                        + (size_t)(((z0+dz)*ID + y0)*ID)*ROWB,
                     YW*ID*ROWB, mb_win);
        }
    }

    // ---- epilogue: scatter accs to out[c][z][y][x] ----
    #pragma unroll
    for (int mt=0; mt<2; mt++){
        const int rbase = w*32 + mt*16 + (l>>2);
        #pragma unroll
        for (int h=0; h<2; h++){
            const int r = rbase + h*8;
            const int yout = r/ID, xp = r - yout*ID;
            if (r < 4*ID && xp < OD){
                const size_t sp = ((size_t)z0*OD + (y0+yout))*OD + xp;
                #pragma unroll
                for (int nt=0; nt<8; nt++){
                    const int n = nt*8 + 2*(l&3);
                    out[(size_t)n*OSZ + sp]     = acc[mt][nt][h*2];
                    out[(size_t)(n+1)*OSZ + sp] = acc[mt][nt][h*2+1];
                }
            }
        }
    }
}

// ---------------------------------------------------------------------------
extern "C" void kernel_launch(void* const* d_in, const int* in_sizes, int n_in,
                              void* d_out, int out_size){
    const float* x      = (const float*)d_in[0];
    const float* weight = (const float*)d_in[1];
    const float* w_sc0  = (const float*)d_in[2];
    const float* w_sc1  = (const float*)d_in[3];
    float* out = (float*)d_out;

    build_w<<<125,256>>>(weight, w_sc0, w_sc1);
    dim3 gx(NSITE/512, 2);
    conv_x<<<gx,256>>>(x);

    cudaFuncSetAttribute(conv_mma, cudaFuncAttributeMaxDynamicSharedMemorySize, SMEMB);
    dim3 grid(13, 52);
    conv_mma<<<grid,256,SMEMB>>>(out);
}

// round 15
// speedup vs baseline: 7.7442x; 1.0014x over previous
#include <cuda_runtime.h>
#include <cuda_fp16.h>
#include <cstdint>
#include <math.h>

#define ID 56
#define OD 52
#define NSITE (ID*ID*ID)           // 175616
#define OSZ (OD*OD*OD)             // 140608
#define PLANE (8*56*64)            // 28672 bytes: one z-plane (8y x 56x x 64B)
#define WINB (5*PLANE)             // 143360
#define SLABB 20480                // 5 taps x 64o x 64B
#define NRING 4
#define CTRL 512
#define SMEMB (CTRL + WINB + NRING*SLABB)   // 225792
#define XCHB (NSITE*64)            // 11239424 bytes per x chunk
#define WCHB 512000                // 125*64*64 bytes per weight chunk
#define WCHH 256000                // halves per weight chunk

__device__ __align__(1024) __half g_xh[2u*NSITE*32];   // [chunk][site][32c] SW64-swizzled
__device__ __align__(1024) __half g_Wh[2u*125*64*32];  // [chunk][tap][o][32c] SW64-swizzled

__device__ __forceinline__ uint32_t swz(uint32_t a){ return a ^ ((a>>3)&0x30u); }
__device__ __forceinline__ uint32_t s2u(const void* p){
    uint32_t a; asm("{ .reg .u64 t; cvta.to.shared.u64 t, %1; cvt.u32.u64 %0, t; }":"=r"(a):"l"(p)); return a;
}
#define MBAR_INIT(a,c) asm volatile("mbarrier.init.shared.b64 [%0], %1;"::"r"(a),"r"(c):"memory")
#define MBAR_TX(a,b)   asm volatile("mbarrier.arrive.expect_tx.shared.b64 _, [%0], %1;"::"r"(a),"r"(b):"memory")
#define MBAR_WAIT(a,p) do{ uint32_t _m=(a),_p=(p); asm volatile( \
    "{\n\t.reg .pred P;\n\tW%=:\n\t" \
    "mbarrier.try_wait.parity.acquire.cta.shared::cta.b64 P, [%0], %1, 0x989680;\n\t" \
    "@P bra.uni D%=;\n\tbra.uni W%=;\n\tD%=:\n\t}"::"r"(_m),"r"(_p):"memory"); }while(0)
#define BULK(dst,src,n,mb) asm volatile( \
    "cp.async.bulk.shared::cluster.global.mbarrier::complete_tx::bytes [%0], [%1], %2, [%3];" \
    ::"r"(dst),"l"(src),"r"(n),"r"(mb):"memory")
#define LDSM_X4(r, a) asm volatile( \
    "ldmatrix.sync.aligned.m8n8.x4.shared.b16 {%0,%1,%2,%3}, [%4];" \
    : "=r"((r)[0]),"=r"((r)[1]),"=r"((r)[2]),"=r"((r)[3]) : "r"(a))
#define MMA16816(d, a, b) asm volatile( \
    "mma.sync.aligned.m16n8k16.row.col.f32.f16.f16.f32 " \
    "{%0,%1,%2,%3}, {%4,%5,%6,%7}, {%8,%9}, {%0,%1,%2,%3};" \
    : "+f"((d)[0]),"+f"((d)[1]),"+f"((d)[2]),"+f"((d)[3]) \
    : "r"((a)[0]),"r"((a)[1]),"r"((a)[2]),"r"((a)[3]), "r"((b)[0]),"r"((b)[1]))

// ---------------- prep: weights -> fp16 swizzled [chunk][tap][o64][c32] ----
__global__ void build_w(const float* __restrict__ weight,
                        const float* __restrict__ w_sc0,
                        const float* __restrict__ w_sc1){
    const int tap = blockIdx.x;
    const int i = tap/25, j = (tap/5)%5, k = tap%5;
    const float rr[5] = {-1.f,-0.5f,0.f,0.5f,1.f};
    const float ri=rr[i], rj=rr[j], rk=rr[k];
    const float d = sqrtf(ri*ri+rj*rj+rk*rk);
    float emb[5]; const float C = 1.14136f*7.389056098930650f;
    #pragma unroll
    for (int t=0;t<5;t++){
        float diff = 4.f*d - (float)t;
        float t1 = diff+1.f, t2 = 1.f-diff;
        float s1 = (t1>0.f)?expf(-1.f/t1):0.f;
        float s2 = (t2>0.f)?expf(-1.f/t2):0.f;
        emb[t] = C*s1*s2;
    }
    const float dn = fmaxf(d,1e-12f);
    const float SQ3 = 1.7320508075688772f;
    float sh[3] = {SQ3*ri/dn, SQ3*rj/dn, SQ3*rk/dn};
    const int tid = threadIdx.x, u = tid>>4, wc = tid&15, col = u*16+wc;
    float w1=0,w2=0,w3=0,w4=0;
    #pragma unroll
    for (int t=0;t<5;t++){
        float e = emb[t];
        w1 += e*weight[t*1024+  0+col]; w2 += e*weight[t*1024+256+col];
        w3 += e*weight[t*1024+512+col]; w4 += e*weight[t*1024+768+col];
    }
    const float PW0=0.17677669529663687f, PW1=0.30618621784789724f, IS3=0.57735026918962576f;
    const bool center = (tap==62);
    auto put = [&](int ci, int o, float v){
        int ch = ci>>5, c = ci&31;
        uint32_t byte = (uint32_t)tap*4096u + (uint32_t)o*64u + (uint32_t)c*2u;
        g_Wh[(uint32_t)ch*WCHH + swz(byte)/2] = __float2half(v);
    };
    float vss = PW0*w1; if (center) vss += 0.25f*w_sc0[u*16+wc];
    put(u, wc, vss);
    #pragma unroll
    for (int kc=0;kc<3;kc++) put(u, 16+wc*3+kc, PW1*IS3*w2*sh[kc]);
    #pragma unroll
    for (int ic=0;ic<3;ic++) put(16+u*3+ic, wc, PW0*IS3*w4*sh[ic]);
    float vv = PW1*IS3*w3; if (center) vv += 0.25f*w_sc1[u*16+wc];
    #pragma unroll
    for (int ic=0;ic<3;ic++)
        #pragma unroll
        for (int jc=0;jc<3;jc++)
            put(16+u*3+ic, 16+wc*3+jc, (ic==jc)?vv:0.f);
}

// ------------- prep: x -> fp16 swizzled [chunk][site][32c] (64B rows) ------
__global__ void __launch_bounds__(256) conv_x(const float* __restrict__ x){
    __shared__ uint32_t sb[16][514];
    const int chunk = blockIdx.y;
    const int site0 = blockIdx.x*512;
    const int tid = threadIdx.x;
    #pragma unroll
    for (int p=0;p<16;p++){
        const float* a = x + (size_t)(chunk*32+2*p)*NSITE + site0;
        const float* b = a + NSITE;
        sb[p][tid]     = ((uint32_t)__half_as_ushort(__float2half(a[tid]))) |
                         ((uint32_t)__half_as_ushort(__float2half(b[tid]))<<16);
        sb[p][tid+256] = ((uint32_t)__half_as_ushort(__float2half(a[tid+256]))) |
                         ((uint32_t)__half_as_ushort(__float2half(b[tid+256]))<<16);
    }
    __syncthreads();
    uint32_t* dst = (uint32_t*)g_xh + (uint32_t)chunk*(XCHB/4);
    #pragma unroll
    for (int it=0;it<32;it++){
        int jdx = tid + it*256;
        int sl = jdx>>4, p = jdx&15;
        uint32_t byte = (uint32_t)(site0+sl)*64u + (uint32_t)p*4u;
        dst[swz(byte)/4] = sb[p][sl];
    }
}

// ---------------------------- main HMMA conv -------------------------------
__global__ void __launch_bounds__(128,1) conv_mma(float* __restrict__ out){
    extern __shared__ __align__(1024) char sm[];
    const uint32_t smb = s2u(sm);
    const int tid = threadIdx.x, w = tid>>5, l = tid&31;
    const uint32_t mb_win = smb;
    const uint32_t win = smb + CTRL;
    const uint32_t slabs = win + WINB;

    if (tid==0){
        MBAR_INIT(mb_win,1);
        #pragma unroll
        for (int q=0;q<NRING;q++) MBAR_INIT(smb+8+q*8,1);
    }
    __syncthreads();

    const int y0 = blockIdx.x*4, z0 = blockIdx.y;
    const char* gW = (const char*)g_Wh;
    const char* gX = (const char*)g_xh;

    if (tid==0){
        MBAR_TX(mb_win, WINB);
        #pragma unroll
        for (int dz=0;dz<5;dz++)
            BULK(win + dz*PLANE,
                 gX + (size_t)((z0+dz)*3136 + y0*56)*64, PLANE, mb_win);
        #pragma unroll
        for (int q=0;q<NRING;q++){
            MBAR_TX(smb+8+q*8, SLABB);
            BULK(slabs + q*SLABB, gW + q*SLABB, SLABB, smb+8+q*8);
        }
    }

    float acc[4][8][4];
    #pragma unroll
    for (int mt=0;mt<4;mt++)
        #pragma unroll
        for (int nt=0;nt<8;nt++)
            #pragma unroll
            for (int q=0;q<4;q++) acc[mt][nt][q] = 0.f;

    // lane-constant logical offsets
    const uint32_t laneA = ((uint32_t)w*64 + (l&15))*64u + ((uint32_t)(l>>4))*16u;
    const uint32_t bL = ((uint32_t)((l&7) + ((l&16)>>1)))*64u + ((uint32_t)(l&8)<<1);
    uint32_t bsw[2];
    bsw[0] = swz(bL);
    bsw[1] = swz(bL + 32u);

    for (int ch=0; ch<2; ch++){
        MBAR_WAIT(mb_win, ch);
        for (int s=0;s<25;s++){
            const int i = ch*25 + s;
            const int q = i & (NRING-1);
            MBAR_WAIT(smb+8+q*8, (i>>2)&1);
            const uint32_t sl = slabs + q*SLABB;
            #pragma unroll
            for (int jt=0;jt<5;jt++){
                const int t = s*5 + jt;
                const int dz = t/25, dy = (t/5)%5, dx = t%5;
                const uint32_t D = (uint32_t)((dz*8+dy)*56 + dx)*64u;
                #pragma unroll
                for (int kk=0;kk<2;kk++){
                    uint32_t bf[16];
                    #pragma unroll
                    for (int g=0; g<4; g++)
                        LDSM_X4(bf + g*4, sl + (uint32_t)jt*4096u + (uint32_t)g*1024u + bsw[kk]);
                    #pragma unroll
                    for (int mt=0; mt<4; mt++){
                        uint32_t af[4];
                        const uint32_t r = laneA + (uint32_t)mt*1024u + D + (uint32_t)kk*32u;
                        LDSM_X4(af, win + swz(r));
                        #pragma unroll
                        for (int nt=0; nt<8; nt++)
                            MMA16816(acc[mt][nt], af, bf + nt*2);
                    }
                }
            }
            __syncthreads();
            if (tid==0){
                const int nx = i + NRING;
                if (nx < 50){
                    MBAR_TX(smb+8+q*8, SLABB);
                    BULK(slabs + q*SLABB,
                         gW + (size_t)(nx/25)*WCHB + (size_t)(nx%25)*SLABB,
                         SLABB, smb+8+q*8);
                }
                if (ch==0 && (s%5)==4){
                    if (s==4) MBAR_TX(mb_win, WINB);
                    const int g = s/5;   // z-plane g of chunk0 is dead now
                    BULK(win + g*PLANE,
                         gX + (size_t)XCHB + (size_t)((z0+g)*3136 + y0*56)*64,
                         PLANE, mb_win);
                }
            }
        }
    }

    // ---- epilogue: scatter accs to out[c][z][y][x] ----
    #pragma unroll
    for (int mt=0; mt<4; mt++){
        const int rbase = w*64 + mt*16 + (l>>2);
        #pragma unroll
        for (int h=0; h<2; h++){
            const int r = rbase + h*8;
            const int yout = r/ID, xp = r - yout*ID;
            if (r < 4*ID && xp < OD){
                const size_t sp = ((size_t)z0*OD + (y0+yout))*OD + xp;
                #pragma unroll
                for (int nt=0; nt<8; nt++){
                    const int n = nt*8 + 2*(l&3);
                    out[(size_t)n*OSZ + sp]     = acc[mt][nt][h*2];
                    out[(size_t)(n+1)*OSZ + sp] = acc[mt][nt][h*2+1];
                }
            }
        }
    }
}

// ---------------------------------------------------------------------------
extern "C" void kernel_launch(void* const* d_in, const int* in_sizes, int n_in,
                              void* d_out, int out_size){
    const float* x      = (const float*)d_in[0];
    const float* weight = (const float*)d_in[1];
    const float* w_sc0  = (const float*)d_in[2];
    const float* w_sc1  = (const float*)d_in[3];
    float* out = (float*)d_out;

    build_w<<<125,256>>>(weight, w_sc0, w_sc1);
    dim3 gx(NSITE/512, 2);
    conv_x<<<gx,256>>>(x);

    cudaFuncSetAttribute(conv_mma, cudaFuncAttributeMaxDynamicSharedMemorySize, SMEMB);
    dim3 grid(13, 52);
    conv_mma<<<grid,128,SMEMB>>>(out);
}